// round 3
// baseline (speedup 1.0000x reference)
#include <cuda_runtime.h>

#define BB 1024
#define SS 512
#define DD 128
#define HH 128
#define G4 512    // 4*H
#define KTOT 256  // D + H
#define NOPS 16
#define BC 8           // samples per CTA
#define NCTA (BB/BC)   // 128
#define NTHR 512
#define NC 88          // weight k-rows cached in smem

// Transposed combined weights: g_Wt[k*512 + g] = W_ih[g][k] (k<128) else W_hh[g][k-128]
__device__ float g_Wt[KTOT * G4];
__device__ float g_bias[G4];

typedef unsigned long long u64;

__device__ __forceinline__ u64 pack2(float x) {
    u64 r; asm("mov.b64 %0,{%1,%1};" : "=l"(r) : "f"(x)); return r;
}
__device__ __forceinline__ u64 fma2(u64 a, u64 b, u64 c) {
    u64 d; asm("fma.rn.f32x2 %0,%1,%2,%3;" : "=l"(d) : "l"(a), "l"(b), "l"(c)); return d;
}
__device__ __forceinline__ void unpack2(u64 v, float& lo, float& hi) {
    asm("mov.b64 {%0,%1},%2;" : "=f"(lo), "=f"(hi) : "l"(v));
}

__global__ void setup_kernel(const float* __restrict__ Wih, const float* __restrict__ Whh,
                             const float* __restrict__ bih, const float* __restrict__ bhh) {
    int idx = blockIdx.x * blockDim.x + threadIdx.x;
    if (idx < KTOT * G4) {
        int k = idx >> 9;
        int g = idx & (G4 - 1);
        g_Wt[idx] = (k < DD) ? Wih[g * DD + k] : Whh[g * HH + (k - DD)];
    }
    if (idx < G4) g_bias[idx] = bih[idx] + bhh[idx];
}

extern "C" __global__ void __launch_bounds__(NTHR, 1)
lstm_kernel(const int* __restrict__ tokens, const int* __restrict__ lengths,
            const float* __restrict__ onehot, const float* __restrict__ emb,
            const float* __restrict__ h0, const float* __restrict__ c0,
            const float* __restrict__ linW, const float* __restrict__ linb,
            float* __restrict__ out) {
    extern __shared__ float sW[];  // NC * 512 floats

    __shared__ __align__(16) float xh[KTOT * BC];  // [k][sample] : x (k<128) then h
    __shared__ float gact[G4 * 9];                 // activated gates, padded stride 9
    __shared__ float cs[HH * 9];                   // cell state, padded
    __shared__ float hl[HH * 9];                   // last-hidden snapshot (relu'd)
    __shared__ int len_s[BC];

    const int tid = threadIdx.x;
    const int base_s = blockIdx.x * BC;

    // cache first NC weight rows into smem
    for (int i = tid; i < NC * G4; i += NTHR) sW[i] = g_Wt[i];

    // init h, c
    if (tid < HH) {
        float h0v = h0[tid], c0v = c0[tid];
#pragma unroll
        for (int s = 0; s < BC; s++) {
            xh[(DD + tid) * BC + s] = h0v;
            cs[tid * 9 + s] = c0v;
        }
    }
    if (tid < BC) len_s[tid] = lengths[base_s + tid];

    const int g = tid;
    const float bias = g_bias[g];
    const bool is_tanh_gate = ((g >> 7) == 2);  // gate order: i, f, g, o
    const int j = tid & (HH - 1);
    const int supd = (tid >> 7) * 2;

    const int gath_s = tid >> 6;           // phase-0 sample
    const int gath_k = (tid & 63) * 2;     // phase-0 dim pair

    __syncthreads();

    for (int t = 0; t < SS; t++) {
        // ---- phase 0: x_t = relu(embedding[token]) ----
        {
            int tok = tokens[(base_s + gath_s) * SS + t];
            float2 e = *(const float2*)(emb + tok * DD + gath_k);
            xh[gath_k * BC + gath_s] = fmaxf(e.x, 0.f);
            xh[(gath_k + 1) * BC + gath_s] = fmaxf(e.y, 0.f);
        }
        __syncthreads();

        // ---- phase 1: gates[g][s] = bias + sum_k W[g][k] * xh[k][s] ----
        u64 a0 = pack2(bias), a1 = a0, a2 = a0, a3 = a0;
#pragma unroll 4
        for (int k = 0; k < NC; k++) {
            u64 wp = pack2(sW[k * G4 + g]);
            ulonglong2 va = *(const ulonglong2*)(xh + k * BC);
            ulonglong2 vb = *(const ulonglong2*)(xh + k * BC + 4);
            a0 = fma2(wp, va.x, a0);
            a1 = fma2(wp, va.y, a1);
            a2 = fma2(wp, vb.x, a2);
            a3 = fma2(wp, vb.y, a3);
        }
#pragma unroll 4
        for (int k = NC; k < KTOT; k++) {
            u64 wp = pack2(g_Wt[k * G4 + g]);
            ulonglong2 va = *(const ulonglong2*)(xh + k * BC);
            ulonglong2 vb = *(const ulonglong2*)(xh + k * BC + 4);
            a0 = fma2(wp, va.x, a0);
            a1 = fma2(wp, va.y, a1);
            a2 = fma2(wp, vb.x, a2);
            a3 = fma2(wp, vb.y, a3);
        }

        // activation + store to gact
        {
            float v[8];
            unpack2(a0, v[0], v[1]);
            unpack2(a1, v[2], v[3]);
            unpack2(a2, v[4], v[5]);
            unpack2(a3, v[6], v[7]);
#pragma unroll
            for (int s = 0; s < 8; s++) {
                float a = v[s];
                float r = is_tanh_gate ? tanhf(a) : (1.f / (1.f + __expf(-a)));
                gact[g * 9 + s] = r;
            }
        }
        __syncthreads();

        // ---- phase 2: c, h update (thread -> (j, 2 samples)) ----
#pragma unroll
        for (int ds = 0; ds < 2; ds++) {
            int s = supd + ds;
            float iv = gact[j * 9 + s];
            float fv = gact[(HH + j) * 9 + s];
            float gv = gact[(2 * HH + j) * 9 + s];
            float ov = gact[(3 * HH + j) * 9 + s];
            float c = cs[j * 9 + s];
            float cn = fmaf(fv, c, iv * gv);
            float hh = ov * tanhf(cn);
            cs[j * 9 + s] = cn;
            xh[(DD + j) * BC + s] = hh;
            if (t == len_s[s] - 1) hl[j * 9 + s] = fmaxf(hh, 0.f);
        }
        __syncthreads();
    }

    // ---- output: logits = [relu(h_last), onehot] @ linW^T + linb ----
    if (tid < BC * 2) {
        int s = tid >> 1, m = tid & 1;
        float acc = linb[m];
#pragma unroll 4
        for (int jj = 0; jj < HH; jj++)
            acc = fmaf(hl[jj * 9 + s], linW[m * (HH + NOPS) + jj], acc);
#pragma unroll
        for (int p = 0; p < NOPS; p++)
            acc = fmaf(onehot[(base_s + s) * NOPS + p], linW[m * (HH + NOPS) + DD + p], acc);
        out[(base_s + s) * 2 + m] = acc;
    }
}

extern "C" void kernel_launch(void* const* d_in, const int* in_sizes, int n_in,
                              void* d_out, int out_size) {
    const int* tokens = (const int*)d_in[0];
    const int* lengths = (const int*)d_in[1];
    const float* onehot = (const float*)d_in[2];
    const float* emb = (const float*)d_in[3];
    const float* Wih = (const float*)d_in[4];
    const float* Whh = (const float*)d_in[5];
    const float* bih = (const float*)d_in[6];
    const float* bhh = (const float*)d_in[7];
    const float* h0 = (const float*)d_in[8];
    const float* c0 = (const float*)d_in[9];
    const float* linW = (const float*)d_in[10];
    const float* linb = (const float*)d_in[11];
    float* out = (float*)d_out;

    setup_kernel<<<(KTOT * G4 + 255) / 256, 256>>>(Wih, Whh, bih, bhh);

    size_t dyn = (size_t)NC * G4 * sizeof(float);
    cudaFuncSetAttribute(lstm_kernel, cudaFuncAttributeMaxDynamicSharedMemorySize, (int)dyn);
    lstm_kernel<<<NCTA, NTHR, dyn>>>(tokens, lengths, onehot, emb, h0, c0, linW, linb, out);
}

// round 8
// speedup vs baseline: 18.1646x; 18.1646x over previous
#include <cuda_runtime.h>
#include <cuda_bf16.h>
#include <cstdint>

#define SS   512
#define G4   512
#define HH   128
#define DD   128
#define VSZ  64000
#define BC   8
#define NCTA 128
#define NOPS 16

typedef unsigned int u32;

// ---------------- device globals ----------------
__device__ __align__(16) __nv_bfloat16 g_Wih_bf[G4 * DD];  // row-major [gate][k]
__device__ __align__(16) __nv_bfloat16 g_Whh_bf[G4 * HH];
__device__ float g_bias[G4];
// xg[token][j*4 + type] fp32: full x-path precomputed with bias
__device__ __align__(16) float g_xg[(size_t)VSZ * G4];  // 131 MB

// ---------------- helpers ----------------
__device__ __forceinline__ u32 smem_u32(const void* p) {
    u32 a;
    asm("{ .reg .u64 t; cvta.to.shared.u64 t, %1; cvt.u32.u64 %0, t; }" : "=r"(a) : "l"(p));
    return a;
}
__device__ __forceinline__ void mma16816(float* d, const u32* a, const u32* b) {
    asm volatile(
        "mma.sync.aligned.m16n8k16.row.col.f32.bf16.bf16.f32 "
        "{%0,%1,%2,%3},{%4,%5,%6,%7},{%8,%9},{%0,%1,%2,%3};"
        : "+f"(d[0]), "+f"(d[1]), "+f"(d[2]), "+f"(d[3])
        : "r"(a[0]), "r"(a[1]), "r"(a[2]), "r"(a[3]), "r"(b[0]), "r"(b[1]));
}
__device__ __forceinline__ void ldsm_x2t(u32* r, u32 addr) {
    asm volatile("ldmatrix.sync.aligned.m8n8.x2.trans.shared.b16 {%0,%1},[%2];"
                 : "=r"(r[0]), "=r"(r[1]) : "r"(addr));
}
__device__ __forceinline__ float ex2_ap(float x) {
    float y; asm("ex2.approx.f32 %0, %1;" : "=f"(y) : "f"(x)); return y;
}
__device__ __forceinline__ float rcp_ap(float x) {
    float y; asm("rcp.approx.f32 %0, %1;" : "=f"(y) : "f"(x)); return y;
}
// accurate sigmoid: 1/(1+e^-x), err ~1e-6
__device__ __forceinline__ float sig_f(float x) {
    return rcp_ap(1.f + ex2_ap(-1.4426950408889634f * x));
}
// accurate tanh: 1 - 2/(1+e^{2x})
__device__ __forceinline__ float tanh_f(float x) {
    return 1.f - 2.f * rcp_ap(1.f + ex2_ap(2.885390081777927f * x));
}

// ---------------- setup: bf16 weights + bias ----------------
__global__ void setup_kernel(const float* __restrict__ Wih, const float* __restrict__ Whh,
                             const float* __restrict__ bih, const float* __restrict__ bhh) {
    int idx = blockIdx.x * blockDim.x + threadIdx.x;  // 0..131071
    int which = idx >> 16;
    int e = idx & 65535;
    if (which == 0)
        g_Wih_bf[e] = __float2bfloat16(Wih[e]);
    else
        g_Whh_bf[e] = __float2bfloat16(Whh[e]);
    if (idx < G4) g_bias[idx] = bih[idx] + bhh[idx];
}

// ---------------- Phase A: xg = W_ih @ relu(emb) + bias, all tokens ----------------
// Each CTA: 128 tokens. B tile: X[d][tok] bf16, pitch 272B (conflict-free ldmatrix).
#define XPITCH 272
__global__ void __launch_bounds__(256, 1)
phaseA_kernel(const float* __restrict__ emb) {
    __shared__ __align__(16) unsigned char sX[128 * XPITCH];
    const int tid = threadIdx.x;
    const int w = tid >> 5, lane = tid & 31;
    const int tokbase = blockIdx.x * 128;

    // gather X = bf16(relu(emb[token]))  ->  sX[d][tok]
    {
        int r = tid >> 1, half = tid & 1;  // token r, dim half
        const float* er = emb + (size_t)(tokbase + r) * DD + half * 64;
#pragma unroll 4
        for (int cc = 0; cc < 64; cc += 4) {
            float4 f = *(const float4*)(er + cc);
            int d0 = half * 64 + cc;
            *(__nv_bfloat16*)(sX + (d0 + 0) * XPITCH + r * 2) = __float2bfloat16(fmaxf(f.x, 0.f));
            *(__nv_bfloat16*)(sX + (d0 + 1) * XPITCH + r * 2) = __float2bfloat16(fmaxf(f.y, 0.f));
            *(__nv_bfloat16*)(sX + (d0 + 2) * XPITCH + r * 2) = __float2bfloat16(fmaxf(f.z, 0.f));
            *(__nv_bfloat16*)(sX + (d0 + 3) * XPITCH + r * 2) = __float2bfloat16(fmaxf(f.w, 0.f));
        }
    }

    // load A fragments (W_ih) into registers: warp w -> m-tiles {w, w+8, w+16, w+24}
    u32 a[4][8][4];
#pragma unroll
    for (int mt = 0; mt < 4; mt++) {
        int g1 = mt * 128 + w * 16 + (lane >> 2);
        int kc = (lane & 3) * 2;
#pragma unroll
        for (int kt = 0; kt < 8; kt++) {
            const __nv_bfloat16* Wp = g_Wih_bf + g1 * DD + kt * 16 + kc;
            a[mt][kt][0] = *(const u32*)(Wp);
            a[mt][kt][1] = *(const u32*)(Wp + 8 * DD);
            a[mt][kt][2] = *(const u32*)(Wp + 8);
            a[mt][kt][3] = *(const u32*)(Wp + 8 * DD + 8);
        }
    }
    // biases for this thread's rows
    float bs[4][2];
#pragma unroll
    for (int mt = 0; mt < 4; mt++) {
        bs[mt][0] = g_bias[mt * 128 + w * 16 + (lane >> 2)];
        bs[mt][1] = g_bias[mt * 128 + w * 16 + (lane >> 2) + 8];
    }
    __syncthreads();

    u32 xb = smem_u32(sX);
    const int jb = w * 16 + (lane >> 2);
    const int n0 = (lane & 3) * 2;

    for (int nt = 0; nt < 16; nt++) {
        u32 bf[8][2];
#pragma unroll
        for (int kt = 0; kt < 8; kt++)
            ldsm_x2t(bf[kt], xb + (kt * 16 + (lane & 15)) * XPITCH + nt * 16);
        float acc[4][4];
#pragma unroll
        for (int mt = 0; mt < 4; mt++) {
            acc[mt][0] = acc[mt][1] = acc[mt][2] = acc[mt][3] = 0.f;
#pragma unroll
            for (int kt = 0; kt < 8; kt++) mma16816(acc[mt], a[mt][kt], bf[kt]);
        }
#pragma unroll
        for (int e = 0; e < 4; e++) {
            int j = jb + (e >> 1) * 8;
            int tok = tokbase + nt * 8 + n0 + (e & 1);
            float4 v;
            v.x = acc[0][e] + bs[0][e >> 1];
            v.y = acc[1][e] + bs[1][e >> 1];
            v.z = acc[2][e] + bs[2][e >> 1];
            v.w = acc[3][e] + bs[3][e >> 1];
            *(float4*)(g_xg + (size_t)tok * G4 + j * 4) = v;
        }
    }
}

// ---------------- recurrent kernel ----------------
__global__ void __launch_bounds__(256, 1)
lstm_rec(const int* __restrict__ tokens, const int* __restrict__ lengths,
         const float* __restrict__ onehot, const float* __restrict__ h0,
         const float* __restrict__ c0, const float* __restrict__ linW,
         const float* __restrict__ linb, float* __restrict__ out) {
    __shared__ __align__(16) unsigned char hb[HH * 16];  // h tile [k][s] bf16, 16B rows
    __shared__ int stok[BC * SS];                        // [s][t]
    __shared__ float shl[BC * HH];

    const int tid = threadIdx.x;
    const int w = tid >> 5, lane = tid & 31;
    const int base_s = blockIdx.x * BC;

    // stage tokens
    for (int i = tid; i < BC * SS; i += 256) {
        int s = i >> 9, t = i & 511;
        stok[s * SS + t] = tokens[(size_t)(base_s + s) * SS + t];
    }
    // init h0 tile
    for (int i = tid; i < HH * BC; i += 256) {
        int j = i >> 3, s = i & 7;
        *(__nv_bfloat16*)(hb + j * 16 + s * 2) = __float2bfloat16(h0[j]);
    }

    // A fragments (W_hh) resident in registers for all 512 steps
    u32 a[4][8][4];
#pragma unroll
    for (int mt = 0; mt < 4; mt++) {
        int g1 = mt * 128 + w * 16 + (lane >> 2);
        int kc = (lane & 3) * 2;
#pragma unroll
        for (int kt = 0; kt < 8; kt++) {
            const __nv_bfloat16* Wp = g_Whh_bf + g1 * HH + kt * 16 + kc;
            a[mt][kt][0] = *(const u32*)(Wp);
            a[mt][kt][1] = *(const u32*)(Wp + 8 * HH);
            a[mt][kt][2] = *(const u32*)(Wp + 8);
            a[mt][kt][3] = *(const u32*)(Wp + 8 * HH + 8);
        }
    }

    const int jb = w * 16 + (lane >> 2);   // row for e<2; +8 for e>=2
    const int s0 = (lane & 3) * 2;         // sample for even e; +1 odd
    u32 hbase = smem_u32(hb);

    float c[4], hl[4];
    int len_[2];
    len_[0] = lengths[base_s + s0];
    len_[1] = lengths[base_s + s0 + 1];
#pragma unroll
    for (int e = 0; e < 4; e++) {
        c[e] = c0[jb + (e >> 1) * 8];
        hl[e] = 0.f;
    }

    // prefetch xg for t=0
    float4 xc[4];
    {
        int t0 = stok[s0 * SS], t1 = stok[(s0 + 1) * SS];
#pragma unroll
        for (int e = 0; e < 4; e++) {
            int j = jb + (e >> 1) * 8;
            int tok = (e & 1) ? t1 : t0;
            xc[e] = *(const float4*)(g_xg + (size_t)tok * G4 + j * 4);
        }
    }

    for (int t = 0; t < SS; t++) {
        __syncthreads();  // h(t) tile ready
        u32 bf[8][2];
#pragma unroll
        for (int kt = 0; kt < 8; kt++)
            ldsm_x2t(bf[kt], hbase + (kt * 16 + (lane & 15)) * 16);
        __syncthreads();  // fragments captured; safe to overwrite h

        // prefetch next step's xg
        float4 xn[4];
        if (t + 1 < SS) {
            int t0 = stok[s0 * SS + t + 1], t1 = stok[(s0 + 1) * SS + t + 1];
#pragma unroll
            for (int e = 0; e < 4; e++) {
                int j = jb + (e >> 1) * 8;
                int tok = (e & 1) ? t1 : t0;
                xn[e] = *(const float4*)(g_xg + (size_t)tok * G4 + j * 4);
            }
        }

        float acc[4][4];
#pragma unroll
        for (int mt = 0; mt < 4; mt++) {
            acc[mt][0] = acc[mt][1] = acc[mt][2] = acc[mt][3] = 0.f;
#pragma unroll
            for (int kt = 0; kt < 8; kt++) mma16816(acc[mt], a[mt][kt], bf[kt]);
        }

#pragma unroll
        for (int e = 0; e < 4; e++) {
            int j = jb + (e >> 1) * 8;
            int s = s0 + (e & 1);
            float pi = acc[0][e] + xc[e].x;
            float pf = acc[1][e] + xc[e].y;
            float pg = acc[2][e] + xc[e].z;
            float po = acc[3][e] + xc[e].w;
            float iv = sig_f(pi), fv = sig_f(pf), gv = tanh_f(pg), ov = sig_f(po);
            c[e] = fmaf(fv, c[e], iv * gv);
            float h = ov * tanh_f(c[e]);
            if (t == len_[e & 1] - 1) hl[e] = fmaxf(h, 0.f);
            *(__nv_bfloat16*)(hb + j * 16 + s * 2) = __float2bfloat16(h);
        }
#pragma unroll
        for (int e = 0; e < 4; e++) xc[e] = xn[e];
    }

    // stash last-hidden, compute head
#pragma unroll
    for (int e = 0; e < 4; e++)
        shl[(s0 + (e & 1)) * HH + jb + (e >> 1) * 8] = hl[e];
    __syncthreads();
    if (tid < BC * 2) {
        int s = tid >> 1, m = tid & 1;
        const float* wrow = linW + m * (HH + NOPS);
        float acc = linb[m];
#pragma unroll 8
        for (int jj = 0; jj < HH; jj++) acc = fmaf(shl[s * HH + jj], wrow[jj], acc);
#pragma unroll
        for (int p = 0; p < NOPS; p++)
            acc = fmaf(onehot[(base_s + s) * NOPS + p], wrow[HH + p], acc);
        out[(base_s + s) * 2 + m] = acc;
    }
}

// ---------------- launch ----------------
extern "C" void kernel_launch(void* const* d_in, const int* in_sizes, int n_in,
                              void* d_out, int out_size) {
    const int* tokens = (const int*)d_in[0];
    const int* lengths = (const int*)d_in[1];
    const float* onehot = (const float*)d_in[2];
    const float* emb = (const float*)d_in[3];
    const float* Wih = (const float*)d_in[4];
    const float* Whh = (const float*)d_in[5];
    const float* bih = (const float*)d_in[6];
    const float* bhh = (const float*)d_in[7];
    const float* h0 = (const float*)d_in[8];
    const float* c0 = (const float*)d_in[9];
    const float* linW = (const float*)d_in[10];
    const float* linb = (const float*)d_in[11];
    float* out = (float*)d_out;

    setup_kernel<<<512, 256>>>(Wih, Whh, bih, bhh);
    phaseA_kernel<<<VSZ / 128, 256>>>(emb);
    lstm_rec<<<NCTA, 256>>>(tokens, lengths, onehot, h0, c0, linW, linb, out);
}

// round 9
// speedup vs baseline: 28.0999x; 1.5470x over previous
#include <cuda_runtime.h>
#include <cuda_bf16.h>
#include <cstdint>

#define SS   512
#define G4   512
#define HH   128
#define DD   128
#define VSZ  64000
#define BC   8
#define NCTA 128
#define NOPS 16

typedef unsigned int u32;
typedef unsigned long long u64;

// ---------------- device globals ----------------
__device__ __align__(16) __nv_bfloat16 g_Wih_bf[G4 * DD];  // row-major [gate][k]
__device__ __align__(16) __nv_bfloat16 g_Whh_bf[G4 * HH];
__device__ float g_bias[G4];
// xg[token][j*4 + type] bf16: full x-path precomputed with bias (i,f,g,o per j)
__device__ __align__(16) __nv_bfloat16 g_xg[(size_t)VSZ * G4];  // 64 MB

// ---------------- helpers ----------------
__device__ __forceinline__ u32 smem_u32(const void* p) {
    u32 a;
    asm("{ .reg .u64 t; cvta.to.shared.u64 t, %1; cvt.u32.u64 %0, t; }" : "=r"(a) : "l"(p));
    return a;
}
__device__ __forceinline__ void mma16816(float* d, const u32* a, const u32* b) {
    asm volatile(
        "mma.sync.aligned.m16n8k16.row.col.f32.bf16.bf16.f32 "
        "{%0,%1,%2,%3},{%4,%5,%6,%7},{%8,%9},{%0,%1,%2,%3};"
        : "+f"(d[0]), "+f"(d[1]), "+f"(d[2]), "+f"(d[3])
        : "r"(a[0]), "r"(a[1]), "r"(a[2]), "r"(a[3]), "r"(b[0]), "r"(b[1]));
}
__device__ __forceinline__ void ldsm_x2t(u32* r, u32 addr) {
    asm volatile("ldmatrix.sync.aligned.m8n8.x2.trans.shared.b16 {%0,%1},[%2];"
                 : "=r"(r[0]), "=r"(r[1]) : "r"(addr));
}
__device__ __forceinline__ float ex2_ap(float x) {
    float y; asm("ex2.approx.f32 %0, %1;" : "=f"(y) : "f"(x)); return y;
}
__device__ __forceinline__ float rcp_ap(float x) {
    float y; asm("rcp.approx.f32 %0, %1;" : "=f"(y) : "f"(x)); return y;
}
__device__ __forceinline__ float tanh_ap(float x) {
    float y; asm("tanh.approx.f32 %0, %1;" : "=f"(y) : "f"(x)); return y;
}
// fast sigmoid via tanh.approx: 1 MUFU + 1 FMA
__device__ __forceinline__ float sig_ap(float x) {
    return fmaf(tanh_ap(x * 0.5f), 0.5f, 0.5f);
}
// accurate tanh: 1 - 2/(1+e^{2x})  (protects the c -> h path)
__device__ __forceinline__ float tanh_acc(float x) {
    return 1.f - 2.f * rcp_ap(1.f + ex2_ap(2.885390081777927f * x));
}
__device__ __forceinline__ float bf_lo(u32 p) { return __uint_as_float(p << 16); }
__device__ __forceinline__ float bf_hi(u32 p) { return __uint_as_float(p & 0xFFFF0000u); }

// ---------------- setup: bf16 weights + bias ----------------
__global__ void setup_kernel(const float* __restrict__ Wih, const float* __restrict__ Whh,
                             const float* __restrict__ bih, const float* __restrict__ bhh) {
    int idx = blockIdx.x * blockDim.x + threadIdx.x;  // 0..131071
    int which = idx >> 16;
    int e = idx & 65535;
    if (which == 0)
        g_Wih_bf[e] = __float2bfloat16(Wih[e]);
    else
        g_Whh_bf[e] = __float2bfloat16(Whh[e]);
    if (idx < G4) g_bias[idx] = bih[idx] + bhh[idx];
}

// ---------------- Phase A: xg = W_ih @ relu(emb) + bias, all tokens ----------------
#define XPITCH 272
__global__ void __launch_bounds__(256, 1)
phaseA_kernel(const float* __restrict__ emb) {
    __shared__ __align__(16) unsigned char sX[128 * XPITCH];
    const int tid = threadIdx.x;
    const int w = tid >> 5, lane = tid & 31;
    const int tokbase = blockIdx.x * 128;

    // gather X = bf16(relu(emb[token]))  ->  sX[d][tok]
    {
        int r = tid >> 1, half = tid & 1;
        const float* er = emb + (size_t)(tokbase + r) * DD + half * 64;
#pragma unroll 4
        for (int cc = 0; cc < 64; cc += 4) {
            float4 f = *(const float4*)(er + cc);
            int d0 = half * 64 + cc;
            *(__nv_bfloat16*)(sX + (d0 + 0) * XPITCH + r * 2) = __float2bfloat16(fmaxf(f.x, 0.f));
            *(__nv_bfloat16*)(sX + (d0 + 1) * XPITCH + r * 2) = __float2bfloat16(fmaxf(f.y, 0.f));
            *(__nv_bfloat16*)(sX + (d0 + 2) * XPITCH + r * 2) = __float2bfloat16(fmaxf(f.z, 0.f));
            *(__nv_bfloat16*)(sX + (d0 + 3) * XPITCH + r * 2) = __float2bfloat16(fmaxf(f.w, 0.f));
        }
    }

    // A fragments (W_ih): warp w -> m-tiles {w, w+8, w+16, w+24}
    u32 a[4][8][4];
#pragma unroll
    for (int mt = 0; mt < 4; mt++) {
        int g1 = mt * 128 + w * 16 + (lane >> 2);
        int kc = (lane & 3) * 2;
#pragma unroll
        for (int kt = 0; kt < 8; kt++) {
            const __nv_bfloat16* Wp = g_Wih_bf + g1 * DD + kt * 16 + kc;
            a[mt][kt][0] = *(const u32*)(Wp);
            a[mt][kt][1] = *(const u32*)(Wp + 8 * DD);
            a[mt][kt][2] = *(const u32*)(Wp + 8);
            a[mt][kt][3] = *(const u32*)(Wp + 8 * DD + 8);
        }
    }
    float bs[4][2];
#pragma unroll
    for (int mt = 0; mt < 4; mt++) {
        bs[mt][0] = g_bias[mt * 128 + w * 16 + (lane >> 2)];
        bs[mt][1] = g_bias[mt * 128 + w * 16 + (lane >> 2) + 8];
    }
    __syncthreads();

    u32 xb = smem_u32(sX);
    const int jb = w * 16 + (lane >> 2);
    const int n0 = (lane & 3) * 2;

    for (int nt = 0; nt < 16; nt++) {
        u32 bf[8][2];
#pragma unroll
        for (int kt = 0; kt < 8; kt++)
            ldsm_x2t(bf[kt], xb + (kt * 16 + (lane & 15)) * XPITCH + nt * 16);
        float acc[4][4];
#pragma unroll
        for (int mt = 0; mt < 4; mt++) {
            acc[mt][0] = acc[mt][1] = acc[mt][2] = acc[mt][3] = 0.f;
#pragma unroll
            for (int kt = 0; kt < 8; kt++) mma16816(acc[mt], a[mt][kt], bf[kt]);
        }
#pragma unroll
        for (int e = 0; e < 4; e++) {
            int j = jb + (e >> 1) * 8;
            int tok = tokbase + nt * 8 + n0 + (e & 1);
            __nv_bfloat162 p0 = __floats2bfloat162_rn(acc[0][e] + bs[0][e >> 1],
                                                      acc[1][e] + bs[1][e >> 1]);
            __nv_bfloat162 p1 = __floats2bfloat162_rn(acc[2][e] + bs[2][e >> 1],
                                                      acc[3][e] + bs[3][e >> 1]);
            uint2 v = make_uint2(*(u32*)&p0, *(u32*)&p1);
            *(uint2*)(g_xg + (size_t)tok * G4 + j * 4) = v;
        }
    }
}

// ---------------- recurrent kernel ----------------
__global__ void __launch_bounds__(256, 1)
lstm_rec(const int* __restrict__ tokens, const int* __restrict__ lengths,
         const float* __restrict__ onehot, const float* __restrict__ h0,
         const float* __restrict__ c0, const float* __restrict__ linW,
         const float* __restrict__ linb, float* __restrict__ out) {
    __shared__ __align__(16) unsigned char hb[2][HH * 16];  // double-buffered h tile
    __shared__ int stok[BC * SS];
    __shared__ float shl[BC * HH];

    const int tid = threadIdx.x;
    const int w = tid >> 5, lane = tid & 31;
    const int base_s = blockIdx.x * BC;

    for (int i = tid; i < BC * SS; i += 256) {
        int s = i >> 9, t = i & 511;
        stok[s * SS + t] = tokens[(size_t)(base_s + s) * SS + t];
    }
    for (int i = tid; i < HH * BC; i += 256) {
        int j = i >> 3, s = i & 7;
        *(__nv_bfloat16*)(hb[0] + j * 16 + s * 2) = __float2bfloat16(h0[j]);
    }

    // A fragments (W_hh) register-resident for all 512 steps
    u32 a[4][8][4];
#pragma unroll
    for (int mt = 0; mt < 4; mt++) {
        int g1 = mt * 128 + w * 16 + (lane >> 2);
        int kc = (lane & 3) * 2;
#pragma unroll
        for (int kt = 0; kt < 8; kt++) {
            const __nv_bfloat16* Wp = g_Whh_bf + g1 * HH + kt * 16 + kc;
            a[mt][kt][0] = *(const u32*)(Wp);
            a[mt][kt][1] = *(const u32*)(Wp + 8 * HH);
            a[mt][kt][2] = *(const u32*)(Wp + 8);
            a[mt][kt][3] = *(const u32*)(Wp + 8 * HH + 8);
        }
    }

    const int jb = w * 16 + (lane >> 2);
    const int s0 = (lane & 3) * 2;
    u32 hbase0 = smem_u32(hb[0]);
    u32 hbase1 = smem_u32(hb[1]);

    float c[4], hl[4];
    int len_[2];
    len_[0] = lengths[base_s + s0];
    len_[1] = lengths[base_s + s0 + 1];
#pragma unroll
    for (int e = 0; e < 4; e++) {
        c[e] = c0[jb + (e >> 1) * 8];
        hl[e] = 0.f;
    }

    // 2-deep xg prefetch queue (bf16x4 per cell = u64)
    u64 x0[4], x1[4];
#pragma unroll
    for (int e = 0; e < 4; e++) {
        int j = jb + (e >> 1) * 8;
        int tokA = stok[(s0 + (e & 1)) * SS + 0];
        x0[e] = *(const u64*)(g_xg + (size_t)tokA * G4 + j * 4);
        int tokB = stok[(s0 + (e & 1)) * SS + 1];
        x1[e] = *(const u64*)(g_xg + (size_t)tokB * G4 + j * 4);
    }
    __syncthreads();

    int p = 0;
    for (int t = 0; t < SS; t++) {
        // prefetch xg for t+2
        u64 x2[4] = {0, 0, 0, 0};
        if (t + 2 < SS) {
#pragma unroll
            for (int e = 0; e < 4; e++) {
                int j = jb + (e >> 1) * 8;
                int tok = stok[(s0 + (e & 1)) * SS + t + 2];
                x2[e] = *(const u64*)(g_xg + (size_t)tok * G4 + j * 4);
            }
        }

        u32 hrd = p ? hbase1 : hbase0;
        unsigned char* hwr = hb[p ^ 1];
        u32 bf[8][2];
#pragma unroll
        for (int kt = 0; kt < 8; kt++)
            ldsm_x2t(bf[kt], hrd + (kt * 16 + (lane & 15)) * 16);

        float acc[4][4];
#pragma unroll
        for (int mt = 0; mt < 4; mt++) {
            acc[mt][0] = acc[mt][1] = acc[mt][2] = acc[mt][3] = 0.f;
#pragma unroll
            for (int kt = 0; kt < 8; kt++) mma16816(acc[mt], a[mt][kt], bf[kt]);
        }

#pragma unroll
        for (int e = 0; e < 4; e++) {
            int j = jb + (e >> 1) * 8;
            int s = s0 + (e & 1);
            u32 lo = (u32)x0[e], hi = (u32)(x0[e] >> 32);
            float pi = acc[0][e] + bf_lo(lo);
            float pf = acc[1][e] + bf_hi(lo);
            float pg = acc[2][e] + bf_lo(hi);
            float po = acc[3][e] + bf_hi(hi);
            float iv = sig_ap(pi), fv = sig_ap(pf), ov = sig_ap(po);
            float gv = tanh_ap(pg);
            c[e] = fmaf(fv, c[e], iv * gv);
            float h = ov * tanh_acc(c[e]);
            if (t == len_[e & 1] - 1) hl[e] = fmaxf(h, 0.f);
            *(__nv_bfloat16*)(hwr + j * 16 + s * 2) = __float2bfloat16(h);
        }
        __syncthreads();  // h(t+1) tile visible; also releases read buffer for rewrite
#pragma unroll
        for (int e = 0; e < 4; e++) { x0[e] = x1[e]; x1[e] = x2[e]; }
        p ^= 1;
    }

#pragma unroll
    for (int e = 0; e < 4; e++)
        shl[(s0 + (e & 1)) * HH + jb + (e >> 1) * 8] = hl[e];
    __syncthreads();
    if (tid < BC * 2) {
        int s = tid >> 1, m = tid & 1;
        const float* wrow = linW + m * (HH + NOPS);
        float acc = linb[m];
#pragma unroll 8
        for (int jj = 0; jj < HH; jj++) acc = fmaf(shl[s * HH + jj], wrow[jj], acc);
#pragma unroll
        for (int pp = 0; pp < NOPS; pp++)
            acc = fmaf(onehot[(base_s + s) * NOPS + pp], wrow[HH + pp], acc);
        out[(base_s + s) * 2 + m] = acc;
    }
}

// ---------------- launch ----------------
extern "C" void kernel_launch(void* const* d_in, const int* in_sizes, int n_in,
                              void* d_out, int out_size) {
    const int* tokens = (const int*)d_in[0];
    const int* lengths = (const int*)d_in[1];
    const float* onehot = (const float*)d_in[2];
    const float* emb = (const float*)d_in[3];
    const float* Wih = (const float*)d_in[4];
    const float* Whh = (const float*)d_in[5];
    const float* bih = (const float*)d_in[6];
    const float* bhh = (const float*)d_in[7];
    const float* h0 = (const float*)d_in[8];
    const float* c0 = (const float*)d_in[9];
    const float* linW = (const float*)d_in[10];
    const float* linb = (const float*)d_in[11];
    float* out = (float*)d_out;

    setup_kernel<<<512, 256>>>(Wih, Whh, bih, bhh);
    phaseA_kernel<<<VSZ / 128, 256>>>(emb);
    lstm_rec<<<NCTA, 256>>>(tokens, lengths, onehot, h0, c0, linW, linb, out);
}